// round 3
// baseline (speedup 1.0000x reference)
#include <cuda_runtime.h>
#include <cuda_bf16.h>

// Problem constants
#define B_   8192
#define M_   50000
#define NU_  16
#define F_   128
#define E_   65536
#define C1_  4096          // rows copied in K3 (alongside scatter)

#define SCATTER_BLOCKS ((E_ * 32) / 512)   // 4096
#define K3_GRID (SCATTER_BLOCKS + C1_)     // 8192
#define K4_GRID (B_ + (M_ - C1_))          // 8192 + 45904 = 54096

// Scratch (device globals — no allocation allowed)
__device__ float4 g_h1agg4[B_ * (F_ / 4)];   // h1_agg  [B,F]
__device__ float4 g_h2agg4[B_ * (F_ / 4)];   // h2_agg  [B,F]
__device__ int    g_winner[M_];              // winning b per V_n row (max b), -1 if untouched

// ---------------------------------------------------------------------------
// K1: init scratch (every replay — deterministic)
// ---------------------------------------------------------------------------
__global__ void init_kernel() {
    int t = blockIdx.x * blockDim.x + threadIdx.x;
    const int NV = B_ * (F_ / 4);  // 262144
    if (t < NV) {
        g_h1agg4[t] = make_float4(0.f, 0.f, 0.f, 0.f);
        g_h2agg4[t] = make_float4(0.f, 0.f, 0.f, 0.f);
    }
    if (t < M_) g_winner[t] = -1;
}

// ---------------------------------------------------------------------------
// K2: winner resolution (last-update-wins == max b wins)
// ---------------------------------------------------------------------------
__global__ void winner_kernel(const int* __restrict__ v_idx) {
    int b = blockIdx.x * blockDim.x + threadIdx.x;
    if (b < B_) atomicMax(&g_winner[v_idx[b]], b);
}

// ---------------------------------------------------------------------------
// Row copy helper: one 512-thread block copies one 8KB V_n row (skip winners)
// ---------------------------------------------------------------------------
__device__ __forceinline__ void copy_row(int row, const float* __restrict__ Vn,
                                         float* __restrict__ vout) {
    if (g_winner[row] >= 0) return;
    const float4* src = (const float4*)(Vn   + (size_t)row * (NU_ * F_));
    float4*       dst = (float4*)      (vout + (size_t)row * (NU_ * F_));
    float4 v = __ldcs(src + threadIdx.x);
    __stcs(dst + threadIdx.x, v);
}

// ---------------------------------------------------------------------------
// K3: fused — blocks [0,4096) segment-sum scatter, blocks [4096,8192) copy rows
// ---------------------------------------------------------------------------
__global__ __launch_bounds__(512)
void k3_scatter_copy(const float4* __restrict__ h1_4,
                     const int*    __restrict__ h1_idx,
                     const float4* __restrict__ h2_4,
                     const int*    __restrict__ h2_idx,
                     const float*  __restrict__ Vn,
                     float*        __restrict__ vout) {
    int bid = blockIdx.x;
    if (bid < SCATTER_BLOCKS) {
        int t = bid * 512 + threadIdx.x;         // t in [0, E*32)
        int e = t >> 5;
        int c = t & 31;
        float4 a = __ldcs(h1_4 + t);
        float4 b = __ldcs(h2_4 + t);
        int ia = __ldg(h1_idx + e) * 32 + c;
        int ib = __ldg(h2_idx + e) * 32 + c;
        atomicAdd(&g_h1agg4[ia], a);
        atomicAdd(&g_h2agg4[ib], b);
    } else {
        copy_row(bid - SCATTER_BLOCKS, Vn, vout);   // rows [0, C1_)
    }
}

// ---------------------------------------------------------------------------
// K4: fused — blocks [0,8192) energy for b=bid, rest copy rows [C1_, M_)
//   energy block: 512 threads = 16 warps, warp u owns candidate state u
// ---------------------------------------------------------------------------
__global__ __launch_bounds__(512)
void k4_energy_copy(const float*  __restrict__ mo,
                    const float*  __restrict__ Vn,
                    const int*    __restrict__ v_idx,
                    const float*  __restrict__ gram,
                    float*        __restrict__ energy_out,
                    float*        __restrict__ vout) {
    int bid = blockIdx.x;
    if (bid >= B_) {
        copy_row(bid - B_ + C1_, Vn, vout);
        return;
    }
    int b    = bid;
    int lane = threadIdx.x & 31;
    int u    = threadIdx.x >> 5;   // 0..15

    __shared__ float ov_s[16], le_s[16], dn_s[16];

    // every thread resolves the row (L1-broadcast loads, no smem stage)
    int row = __ldg(v_idx + b);

    // independent loads issued up-front for MLP
    const float4* vrow = (const float4*)(Vn + ((size_t)row * NU_ + u) * F_);
    float4 v  = vrow[lane];
    int    i  = b * 32 + lane;
    float4 m  = __ldg((const float4*)mo + i);
    float4 a1 = g_h1agg4[i];
    float4 a2 = g_h2agg4[i];

    float4 f = make_float4(m.x + a1.x, m.y + a1.y, m.z + a1.z, m.w + a1.w); // feats
    float4 g = make_float4(f.x + a2.x, f.y + a2.y, f.z + a2.z, f.w + a2.w); // feats+h2

    float ov = v.x * m.x + v.y * m.y + v.z * m.z + v.w * m.w;   // overlap partial
    float le = v.x * g.x + v.y * g.y + v.z * g.z + v.w * g.w;   // loc_energy partial
    #pragma unroll
    for (int o = 16; o; o >>= 1) {
        ov += __shfl_xor_sync(0xFFFFFFFF, ov, o);
        le += __shfl_xor_sync(0xFFFFFFFF, le, o);
    }
    if (lane == 0) { ov_s[u] = ov; le_s[u] = le; }
    __syncthreads();

    // warp 0: denom = gram[b] @ overlap (16x16 matvec), p-weights, energy
    if (u == 0) {
        float d = 0.f, l = 0.f;
        if (lane < 16) {
            const float* gr = gram + (size_t)b * (NU_ * NU_) + lane * NU_;
            #pragma unroll
            for (int vv = 0; vv < 16; vv++) d += gr[vv] * ov_s[vv];
            l = le_s[lane];
        }
        float d2 = d * d;
        float ns = l * d2;   // lanes >=16 contribute 0
        float ds = d2;
        #pragma unroll
        for (int o = 16; o; o >>= 1) {
            ns += __shfl_xor_sync(0xFFFFFFFF, ns, o);
            ds += __shfl_xor_sync(0xFFFFFFFF, ds, o);
        }
        if (lane < 16) dn_s[lane] = d;
        if (lane == 0) energy_out[b] = ns / ds;
    }
    __syncthreads();

    // winner block writes top_states = tanh(V + denom[u]*feats)
    if (g_winner[row] == b) {
        float  dn = dn_s[u];
        float4 t;
        t.x = tanhf(v.x + dn * f.x);
        t.y = tanhf(v.y + dn * f.y);
        t.z = tanhf(v.z + dn * f.z);
        t.w = tanhf(v.w + dn * f.w);
        __stcs((float4*)(vout + ((size_t)row * NU_ + u) * F_) + lane, t);
    }
}

// ---------------------------------------------------------------------------
extern "C" void kernel_launch(void* const* d_in, const int* in_sizes, int n_in,
                              void* d_out, int out_size) {
    const float* mo    = (const float*)d_in[0];
    const float* Vn    = (const float*)d_in[1];
    const int*   vidx  = (const int*)  d_in[2];
    const float* h1    = (const float*)d_in[3];
    const int*   h1i   = (const int*)  d_in[4];
    const float* h2    = (const float*)d_in[5];
    const int*   h2i   = (const int*)  d_in[6];
    const float* gram  = (const float*)d_in[7];

    float* energy = (float*)d_out;        // [B]
    float* vout   = energy + B_;          // [M, NU, F]

    {   // K1: zero aggregates, winner=-1
        int n = B_ * (F_ / 4);            // 262144 (>= M_)
        init_kernel<<<(n + 511) / 512, 512>>>();
    }
    // K2: resolve winners
    winner_kernel<<<(B_ + 255) / 256, 256>>>(vidx);

    // K3: scatter ∥ copy[0, C1)
    k3_scatter_copy<<<K3_GRID, 512>>>(
        (const float4*)h1, h1i, (const float4*)h2, h2i, Vn, vout);

    // K4: energy ∥ copy[C1, M)
    k4_energy_copy<<<K4_GRID, 512>>>(mo, Vn, vidx, gram, energy, vout);
}

// round 4
// speedup vs baseline: 1.0425x; 1.0425x over previous
#include <cuda_runtime.h>
#include <cuda_bf16.h>

// Problem constants
#define B_   8192
#define M_   50000
#define NU_  16
#define F_   128
#define E_   65536
#define C1_  4096          // rows copied in K3 (alongside scatter)

#define SCATTER_BLOCKS ((E_ * 32) / 512)   // 4096
#define K3_GRID (SCATTER_BLOCKS + C1_)     // 8192
#define K4_GRID (B_ + (M_ - C1_))          // 8192 + 45904 = 54096

// Scratch (device globals — no allocation allowed)
__device__ float4 g_h1agg4[B_ * (F_ / 4)];   // h1_agg  [B,F]
__device__ float4 g_h2agg4[B_ * (F_ / 4)];   // h2_agg  [B,F]
__device__ int    g_winner[M_];              // winning b per V_n row (max b), -1 if untouched

// ---------------------------------------------------------------------------
// K1: init scratch (every replay — deterministic)
// ---------------------------------------------------------------------------
__global__ void init_kernel() {
    int t = blockIdx.x * blockDim.x + threadIdx.x;
    const int NV = B_ * (F_ / 4);  // 262144
    if (t < NV) {
        g_h1agg4[t] = make_float4(0.f, 0.f, 0.f, 0.f);
        g_h2agg4[t] = make_float4(0.f, 0.f, 0.f, 0.f);
    }
    if (t < M_) g_winner[t] = -1;
}

// ---------------------------------------------------------------------------
// K2: winner resolution (last-update-wins == max b wins)
// ---------------------------------------------------------------------------
__global__ void winner_kernel(const int* __restrict__ v_idx) {
    int b = blockIdx.x * blockDim.x + threadIdx.x;
    if (b < B_) atomicMax(&g_winner[v_idx[b]], b);
}

// ---------------------------------------------------------------------------
// Row copy helper: one 512-thread block copies one 8KB V_n row (skip winners)
// ---------------------------------------------------------------------------
__device__ __forceinline__ void copy_row(int row, const float* __restrict__ Vn,
                                         float* __restrict__ vout) {
    if (g_winner[row] >= 0) return;
    const float4* src = (const float4*)(Vn   + (size_t)row * (NU_ * F_));
    float4*       dst = (float4*)      (vout + (size_t)row * (NU_ * F_));
    float4 v = __ldcs(src + threadIdx.x);
    __stcs(dst + threadIdx.x, v);
}

// ---------------------------------------------------------------------------
// K3: fused, parity-striped — even bids scatter, odd bids copy rows [0, C1_)
// ---------------------------------------------------------------------------
__global__ __launch_bounds__(512)
void k3_scatter_copy(const float4* __restrict__ h1_4,
                     const int*    __restrict__ h1_idx,
                     const float4* __restrict__ h2_4,
                     const int*    __restrict__ h2_idx,
                     const float*  __restrict__ Vn,
                     float*        __restrict__ vout) {
    int bid = blockIdx.x;
    if ((bid & 1) == 0) {
        int t = (bid >> 1) * 512 + threadIdx.x;  // t in [0, E*32)
        int e = t >> 5;
        int c = t & 31;
        float4 a = __ldcs(h1_4 + t);
        float4 b = __ldcs(h2_4 + t);
        int ia = __ldg(h1_idx + e) * 32 + c;
        int ib = __ldg(h2_idx + e) * 32 + c;
        atomicAdd(&g_h1agg4[ia], a);
        atomicAdd(&g_h2agg4[ib], b);
    } else {
        copy_row(bid >> 1, Vn, vout);            // rows [0, C1_)
    }
}

// ---------------------------------------------------------------------------
// K4: fused, striped — bids with (bid%6==0 && bid/6<B_) do energy for b=bid/6,
//     all other bids copy rows [C1_, M_). Every wave ~= 5/6 copy, 1/6 energy.
// ---------------------------------------------------------------------------
__global__ __launch_bounds__(512)
void k4_energy_copy(const float*  __restrict__ mo,
                    const float*  __restrict__ Vn,
                    const int*    __restrict__ v_idx,
                    const float*  __restrict__ gram,
                    float*        __restrict__ energy_out,
                    float*        __restrict__ vout) {
    int bid = blockIdx.x;
    bool is_energy = ((bid % 6) == 0) && ((bid / 6) < B_);
    if (!is_energy) {
        // copy index = bid minus #energy blocks before bid
        int n_e = min((bid + 5) / 6, B_);
        copy_row(C1_ + (bid - n_e), Vn, vout);
        return;
    }
    int b    = bid / 6;
    int lane = threadIdx.x & 31;
    int u    = threadIdx.x >> 5;   // 0..15

    __shared__ float ov_s[16], le_s[16], dn_s[16];

    int row = __ldg(v_idx + b);

    // independent loads issued up-front for MLP
    const float4* vrow = (const float4*)(Vn + ((size_t)row * NU_ + u) * F_);
    float4 v  = vrow[lane];
    int    i  = b * 32 + lane;
    float4 m  = __ldg((const float4*)mo + i);
    float4 a1 = g_h1agg4[i];
    float4 a2 = g_h2agg4[i];

    float4 f = make_float4(m.x + a1.x, m.y + a1.y, m.z + a1.z, m.w + a1.w); // feats
    float4 g = make_float4(f.x + a2.x, f.y + a2.y, f.z + a2.z, f.w + a2.w); // feats+h2

    float ov = v.x * m.x + v.y * m.y + v.z * m.z + v.w * m.w;   // overlap partial
    float le = v.x * g.x + v.y * g.y + v.z * g.z + v.w * g.w;   // loc_energy partial
    #pragma unroll
    for (int o = 16; o; o >>= 1) {
        ov += __shfl_xor_sync(0xFFFFFFFF, ov, o);
        le += __shfl_xor_sync(0xFFFFFFFF, le, o);
    }
    if (lane == 0) { ov_s[u] = ov; le_s[u] = le; }
    __syncthreads();

    // warp 0: denom = gram[b] @ overlap (16x16 matvec), p-weights, energy
    if (u == 0) {
        float d = 0.f, l = 0.f;
        if (lane < 16) {
            const float* gr = gram + (size_t)b * (NU_ * NU_) + lane * NU_;
            #pragma unroll
            for (int vv = 0; vv < 16; vv++) d += gr[vv] * ov_s[vv];
            l = le_s[lane];
        }
        float d2 = d * d;
        float ns = l * d2;   // lanes >=16 contribute 0
        float ds = d2;
        #pragma unroll
        for (int o = 16; o; o >>= 1) {
            ns += __shfl_xor_sync(0xFFFFFFFF, ns, o);
            ds += __shfl_xor_sync(0xFFFFFFFF, ds, o);
        }
        if (lane < 16) dn_s[lane] = d;
        if (lane == 0) energy_out[b] = ns / ds;
    }
    __syncthreads();

    // winner block writes top_states = tanh(V + denom[u]*feats)
    if (g_winner[row] == b) {
        float  dn = dn_s[u];
        float4 t;
        t.x = tanhf(v.x + dn * f.x);
        t.y = tanhf(v.y + dn * f.y);
        t.z = tanhf(v.z + dn * f.z);
        t.w = tanhf(v.w + dn * f.w);
        __stcs((float4*)(vout + ((size_t)row * NU_ + u) * F_) + lane, t);
    }
}

// ---------------------------------------------------------------------------
extern "C" void kernel_launch(void* const* d_in, const int* in_sizes, int n_in,
                              void* d_out, int out_size) {
    const float* mo    = (const float*)d_in[0];
    const float* Vn    = (const float*)d_in[1];
    const int*   vidx  = (const int*)  d_in[2];
    const float* h1    = (const float*)d_in[3];
    const int*   h1i   = (const int*)  d_in[4];
    const float* h2    = (const float*)d_in[5];
    const int*   h2i   = (const int*)  d_in[6];
    const float* gram  = (const float*)d_in[7];

    float* energy = (float*)d_out;        // [B]
    float* vout   = energy + B_;          // [M, NU, F]

    {   // K1: zero aggregates, winner=-1
        int n = B_ * (F_ / 4);            // 262144 (>= M_)
        init_kernel<<<(n + 511) / 512, 512>>>();
    }
    // K2: resolve winners
    winner_kernel<<<(B_ + 255) / 256, 256>>>(vidx);

    // K3: scatter ∥ copy[0, C1), parity-striped
    k3_scatter_copy<<<K3_GRID, 512>>>(
        (const float4*)h1, h1i, (const float4*)h2, h2i, Vn, vout);

    // K4: energy ∥ copy[C1, M), 1-in-6 striped
    k4_energy_copy<<<K4_GRID, 512>>>(mo, Vn, vidx, gram, energy, vout);
}